// round 5
// baseline (speedup 1.0000x reference)
#include <cuda_runtime.h>
#include <cstdint>

// ---------------------------------------------------------------------------
// HandGNNEncoder: 2-layer GCN over fixed 21-node skeleton + mean pool.
//   y[t]   = (A_norm @ x)[t]                 (sparse, <=3 nz/row, consts)
//   H[t,d] = relu(y[t,.] @ W1 + b1)
//   p[d]   = sum_t c[t] * H[t,d]             (c = column-mean of A_norm)
//   out    = p @ W2 + b2
// f32x2-packed; occ-4 single balanced wave (592 blocks, regs<=64).
// ---------------------------------------------------------------------------

typedef unsigned long long ull;

__device__ __forceinline__ ull pk2(float lo, float hi) {
    ull r; asm("mov.b64 %0, {%1, %2};" : "=l"(r) : "f"(lo), "f"(hi)); return r;
}
__device__ __forceinline__ void up2(ull v, float& lo, float& hi) {
    asm("mov.b64 {%0, %1}, %2;" : "=f"(lo), "=f"(hi) : "l"(v));
}
__device__ __forceinline__ ull fma2(ull a, ull b, ull c) {
    ull d; asm("fma.rn.f32x2 %0, %1, %2, %3;" : "=l"(d) : "l"(a), "l"(b), "l"(c)); return d;
}
__device__ __forceinline__ ull add2(ull a, ull b) {
    ull d; asm("add.rn.f32x2 %0, %1, %2;" : "=l"(d) : "l"(a), "l"(b)); return d;
}

#define R2  0.70710678118654752440f   // 1/sqrt(2)
#define R3  0.57735026918962576451f   // 1/sqrt(3)
#define TH  (1.0f/3.0f)
#define W23 (R2*R3)

// (column sums of A_norm / 21) * 0.5  -- the 0.5 absorbs (h+|h|)=2*relu
__device__ __constant__ float cPoolH[21] = {
    0.5f*(1.0f + 2.0f*R2 + 3.0f*R3)/21.0f,
    0.5f/21.0f, 0.5f/21.0f, 0.5f/21.0f, 0.25f/21.0f,
    0.5f*(1.0f + W23)/21.0f,     0.5f/21.0f, 0.5f/21.0f, 0.25f/21.0f,
    0.5f*(2.0f/3.0f + W23)/21.0f,0.5f/21.0f, 0.5f/21.0f, 0.25f/21.0f,
    0.5f*(2.0f/3.0f + W23)/21.0f,0.5f/21.0f, 0.5f/21.0f, 0.25f/21.0f,
    0.5f*(1.0f/3.0f + W23)/21.0f,0.5f/21.0f, 0.5f/21.0f, 0.25f/21.0f,
};

// sparse rows of A_norm: up to 3 (src, weight) entries per target node (0-pad)
__device__ __constant__ int cIdx[63] = {
    0,0,0,   1,0,0,   2,1,0,   3,2,0,   4,3,0,
    5,0,0,   6,5,0,   7,6,0,   8,7,0,
    9,0,5,   10,9,0,  11,10,0, 12,11,0,
    13,0,9,  14,13,0, 15,14,0, 16,15,0,
    17,0,13, 18,17,0, 19,18,0, 20,19,0
};
__device__ __constant__ float cWt[63] = {
    1.0f,0.f,0.f,   0.5f,R2,0.f,   0.5f,0.5f,0.f, 0.5f,0.5f,0.f, 0.5f,0.5f,0.f,
    0.5f,R2,0.f,    0.5f,0.5f,0.f, 0.5f,0.5f,0.f, 0.5f,0.5f,0.f,
    TH,R3,W23,      0.5f,W23,0.f,  0.5f,0.5f,0.f, 0.5f,0.5f,0.f,
    TH,R3,TH,       0.5f,W23,0.f,  0.5f,0.5f,0.f, 0.5f,0.5f,0.f,
    TH,R3,TH,       0.5f,W23,0.f,  0.5f,0.5f,0.f, 0.5f,0.5f,0.f
};

#define NWARP 8
#define THREADS 256
#define FULLMASK 0xffffffffu
#define ABSMASK 0x7fffffff7fffffffULL

__global__ __launch_bounds__(256, 4)
void gnn_kernel(const float* __restrict__ x,
                const float* __restrict__ W1,
                const float* __restrict__ b1,
                const float* __restrict__ W2,
                const float* __restrict__ b2,
                float* __restrict__ out,
                int nquad, int G)
{
    // W2 staged k-pair-packed:
    //  W2A[m][ln] = { pk2(W2[2m][4l],W2[2m+1][4l]),   pk2(.., col 4l+1) }
    //  W2B[m][ln] = cols 4l+2, 4l+3
    __shared__ ulonglong2 W2A[32][32];
    __shared__ ulonglong2 W2B[32][32];
    __shared__ __align__(8) float psh[NWARP][4][64];   // pooled 64-vec, k-major
    __shared__ __align__(8) float yxs[NWARP][21][4];   // aggregated x coord [t][j]
    __shared__ __align__(8) float yys[NWARP][21][4];   // aggregated y coord [t][j]

    const int tid  = threadIdx.x;
    const int lane = tid & 31;
    const int warp = tid >> 5;

    // ---- stage W2 into shared, k-pair packed ----
    for (int idx = tid; idx < 2048; idx += THREADS) {
        int arr = idx & 1;
        int ln  = (idx >> 1) & 31;
        int m   = idx >> 6;
        int c   = 4*ln + 2*arr;
        float2 r0 = *(const float2*)(W2 + (2*m)   * 128 + c);
        float2 r1 = *(const float2*)(W2 + (2*m+1) * 128 + c);
        ulonglong2 v;
        v.x = pk2(r0.x, r1.x);
        v.y = pk2(r0.y, r1.y);
        (arr ? W2B : W2A)[m][ln] = v;
    }

    // per-lane W1/b1, duplicated into both f32x2 halves
    const ull w1a0d = pk2(W1[lane],      W1[lane]);
    const ull w1a1d = pk2(W1[64 + lane], W1[64 + lane]);
    const ull w1b0d = pk2(W1[32 + lane], W1[32 + lane]);
    const ull w1b1d = pk2(W1[96 + lane], W1[96 + lane]);
    const ull b1ad  = pk2(b1[lane],      b1[lane]);
    const ull b1bd  = pk2(b1[32 + lane], b1[32 + lane]);

    // stage-1 sparse row of this lane (lane == target node t)
    int s0 = 0, s1 = 0, s2 = 0;
    float aw0 = 0.f, aw1 = 0.f, aw2 = 0.f;
    if (lane < 21) {
        s0  = cIdx[lane*3];  s1  = cIdx[lane*3+1];  s2  = cIdx[lane*3+2];
        aw0 = cWt[lane*3];   aw1 = cWt[lane*3+1];   aw2 = cWt[lane*3+2];
    }

    __syncthreads();

    const int wid  = blockIdx.x * NWARP + warp;
    const int totw = gridDim.x * NWARP;

    for (int q = wid; q < nquad; q += totw) {
        const int g0 = q * 4;

        // ---- stage 1: y = A_norm @ x via shuffles (one graph live at a time) ----
        #pragma unroll
        for (int j = 0; j < 4; j++) {
            const int g = g0 + j;
            float2 xv = (lane < 21 && g < G)
                        ? ((const float2*)x)[(size_t)g * 21 + lane]
                        : make_float2(0.f, 0.f);
            float xs0x = __shfl_sync(FULLMASK, xv.x, s0);
            float xs0y = __shfl_sync(FULLMASK, xv.y, s0);
            float xs1x = __shfl_sync(FULLMASK, xv.x, s1);
            float xs1y = __shfl_sync(FULLMASK, xv.y, s1);
            float xs2x = __shfl_sync(FULLMASK, xv.x, s2);
            float xs2y = __shfl_sync(FULLMASK, xv.y, s2);
            if (lane < 21) {
                yxs[warp][lane][j] = fmaf(aw2, xs2x, fmaf(aw1, xs1x, aw0 * xs0x));
                yys[warp][lane][j] = fmaf(aw2, xs2y, fmaf(aw1, xs1y, aw0 * xs0y));
            }
        }
        __syncwarp();

        // ---- stage 2: p = c^T relu(y@W1 + b1), packed over graph pairs ----
        {
            ull pA[2] = {0ull, 0ull}, pB[2] = {0ull, 0ull};
            #pragma unroll
            for (int t = 0; t < 21; t++) {
                float ch = cPoolH[t];
                ull ct2 = pk2(ch, ch);
                #pragma unroll
                for (int jp = 0; jp < 2; jp++) {
                    ull x2 = *(const ull*)&yxs[warp][t][2*jp];
                    ull y2 = *(const ull*)&yys[warp][t][2*jp];
                    ull ha = fma2(x2, w1a0d, b1ad);
                    ha = fma2(y2, w1a1d, ha);
                    ha = add2(ha, ha & ABSMASK);        // 2*relu(ha)
                    pA[jp] = fma2(ct2, ha, pA[jp]);     // ct2 already halved
                    ull hb = fma2(x2, w1b0d, b1bd);
                    hb = fma2(y2, w1b1d, hb);
                    hb = add2(hb, hb & ABSMASK);
                    pB[jp] = fma2(ct2, hb, pB[jp]);
                }
            }
            #pragma unroll
            for (int jp = 0; jp < 2; jp++) {
                float lo, hi;
                up2(pA[jp], lo, hi);
                psh[warp][2*jp][lane]        = lo;
                psh[warp][2*jp+1][lane]      = hi;
                up2(pB[jp], lo, hi);
                psh[warp][2*jp][lane + 32]   = lo;
                psh[warp][2*jp+1][lane + 32] = hi;
            }
        }
        __syncwarp();

        // ---- stage 3: out = p @ W2 + b2, two graph-pair passes (acc[2][4]) ----
        const float4 b2v = ((const float4*)b2)[lane];
        #pragma unroll
        for (int jp = 0; jp < 2; jp++) {
            ull acc[2][4];
            #pragma unroll
            for (int jj = 0; jj < 2; jj++)
                #pragma unroll
                for (int c = 0; c < 4; c++) acc[jj][c] = 0ull;

            #pragma unroll 8
            for (int m = 0; m < 32; m++) {
                ulonglong2 wA = W2A[m][lane];   // cols 4l, 4l+1 (k-pair packed)
                ulonglong2 wB = W2B[m][lane];   // cols 4l+2, 4l+3
                #pragma unroll
                for (int jj = 0; jj < 2; jj++) {
                    ull p2 = *(const ull*)&psh[warp][2*jp + jj][2*m];
                    acc[jj][0] = fma2(p2, wA.x, acc[jj][0]);
                    acc[jj][1] = fma2(p2, wA.y, acc[jj][1]);
                    acc[jj][2] = fma2(p2, wB.x, acc[jj][2]);
                    acc[jj][3] = fma2(p2, wB.y, acc[jj][3]);
                }
            }

            #pragma unroll
            for (int jj = 0; jj < 2; jj++) {
                const int g = g0 + 2*jp + jj;
                if (g < G) {
                    float lo, hi;
                    float4 o;
                    up2(acc[jj][0], lo, hi); o.x = (lo + hi) + b2v.x;
                    up2(acc[jj][1], lo, hi); o.y = (lo + hi) + b2v.y;
                    up2(acc[jj][2], lo, hi); o.z = (lo + hi) + b2v.z;
                    up2(acc[jj][3], lo, hi); o.w = (lo + hi) + b2v.w;
                    ((float4*)out)[(size_t)g * 32 + lane] = o;
                }
            }
        }
        __syncwarp();   // protect yxs/yys/psh before next iteration rewrites
    }
}

extern "C" void kernel_launch(void* const* d_in, const int* in_sizes, int n_in,
                              void* d_out, int out_size) {
    const float* x  = (const float*)d_in[0];
    const float* W1 = (const float*)d_in[1];
    const float* b1 = (const float*)d_in[2];
    const float* W2 = (const float*)d_in[3];
    const float* b2 = (const float*)d_in[4];
    float* out = (float*)d_out;

    const int G = in_sizes[0] / 42;         // graphs = B*S
    const int nquad = (G + 3) / 4;

    // 592 = 4 blocks/SM x 148 SMs -> single full wave under launch_bounds(256,4);
    // grid-stride balances quads across all warps.
    gnn_kernel<<<592, THREADS>>>(x, W1, b1, W2, b2, out, nquad, G);
}

// round 6
// speedup vs baseline: 1.2807x; 1.2807x over previous
#include <cuda_runtime.h>
#include <cstdint>

// ---------------------------------------------------------------------------
// HandGNNEncoder: 2-layer GCN over fixed 21-node skeleton + mean pool.
//   y[t]   = (A_norm @ x)[t]              (sparse, <=3 nz/row, consts)
//   p[d]   = sum_t c[t]*relu(y[t]@W1+b1)[d]
//   out    = p @ W2 + b2
// One warp = 8 graphs, exactly once (single wave, 512 CTAs, occ 4).
// f32x2 packed over graph pairs; W2 read once per 8 graphs; p via 2
// broadcast LDS.128 per k. Stage-2 y values travel by shfl (no ysh).
// ---------------------------------------------------------------------------

typedef unsigned long long ull;

__device__ __forceinline__ ull pk2(float lo, float hi) {
    ull r; asm("mov.b64 %0, {%1, %2};" : "=l"(r) : "f"(lo), "f"(hi)); return r;
}
__device__ __forceinline__ void up2(ull v, float& lo, float& hi) {
    asm("mov.b64 {%0, %1}, %2;" : "=f"(lo), "=f"(hi) : "l"(v));
}
__device__ __forceinline__ ull fma2(ull a, ull b, ull c) {
    ull d; asm("fma.rn.f32x2 %0, %1, %2, %3;" : "=l"(d) : "l"(a), "l"(b), "l"(c)); return d;
}
__device__ __forceinline__ ull add2(ull a, ull b) {
    ull d; asm("add.rn.f32x2 %0, %1, %2;" : "=l"(d) : "l"(a), "l"(b)); return d;
}

#define R2  0.70710678118654752440f
#define R3  0.57735026918962576451f
#define TH  (1.0f/3.0f)
#define W23 (R2*R3)

// (column sums of A_norm / 21) * 0.5 -- the 0.5 absorbs (h+|h|)=2*relu
__device__ __constant__ float cPoolH[21] = {
    0.5f*(1.0f + 2.0f*R2 + 3.0f*R3)/21.0f,
    0.5f/21.0f, 0.5f/21.0f, 0.5f/21.0f, 0.25f/21.0f,
    0.5f*(1.0f + W23)/21.0f,     0.5f/21.0f, 0.5f/21.0f, 0.25f/21.0f,
    0.5f*(2.0f/3.0f + W23)/21.0f,0.5f/21.0f, 0.5f/21.0f, 0.25f/21.0f,
    0.5f*(2.0f/3.0f + W23)/21.0f,0.5f/21.0f, 0.5f/21.0f, 0.25f/21.0f,
    0.5f*(1.0f/3.0f + W23)/21.0f,0.5f/21.0f, 0.5f/21.0f, 0.25f/21.0f,
};
__device__ __constant__ int cIdx[63] = {
    0,0,0,   1,0,0,   2,1,0,   3,2,0,   4,3,0,
    5,0,0,   6,5,0,   7,6,0,   8,7,0,
    9,0,5,   10,9,0,  11,10,0, 12,11,0,
    13,0,9,  14,13,0, 15,14,0, 16,15,0,
    17,0,13, 18,17,0, 19,18,0, 20,19,0
};
__device__ __constant__ float cWt[63] = {
    1.0f,0.f,0.f,   0.5f,R2,0.f,   0.5f,0.5f,0.f, 0.5f,0.5f,0.f, 0.5f,0.5f,0.f,
    0.5f,R2,0.f,    0.5f,0.5f,0.f, 0.5f,0.5f,0.f, 0.5f,0.5f,0.f,
    TH,R3,W23,      0.5f,W23,0.f,  0.5f,0.5f,0.f, 0.5f,0.5f,0.f,
    TH,R3,TH,       0.5f,W23,0.f,  0.5f,0.5f,0.f, 0.5f,0.5f,0.f,
    TH,R3,TH,       0.5f,W23,0.f,  0.5f,0.5f,0.f, 0.5f,0.5f,0.f
};

#define NWARP 8
#define THREADS 256
#define FULLMASK 0xffffffffu
#define ABSMASK 0x7fffffff7fffffffULL

__global__ __launch_bounds__(256, 4)
void gnn_kernel(const float* __restrict__ x,
                const float* __restrict__ W1,
                const float* __restrict__ b1,
                const float* __restrict__ W2,
                const float* __restrict__ b2,
                float* __restrict__ out,
                int G)
{
    // 48KB static shared exactly: W2 (32KB) + psh (16KB)
    __shared__ __align__(16) float4 W2s[64*32];          // W2s[k*32+ln] = W2[k][4ln..4ln+3]
    __shared__ __align__(16) float  psh[NWARP][64][8];   // p[k][graph j]

    const int tid  = threadIdx.x;
    const int lane = tid & 31;
    const int warp = tid >> 5;

    // ---- stage W2 into shared (straight float4 copy; layout coincides) ----
    #pragma unroll
    for (int i = 0; i < 8; i++)
        W2s[tid + i*THREADS] = ((const float4*)W2)[tid + i*THREADS];

    // per-lane W1/b1, duplicated into both f32x2 halves (lane owns dims {l, l+32})
    const ull w1a0d = pk2(W1[lane],      W1[lane]);
    const ull w1a1d = pk2(W1[64 + lane], W1[64 + lane]);
    const ull w1b0d = pk2(W1[32 + lane], W1[32 + lane]);
    const ull w1b1d = pk2(W1[96 + lane], W1[96 + lane]);
    const ull b1ad  = pk2(b1[lane],      b1[lane]);
    const ull b1bd  = pk2(b1[32 + lane], b1[32 + lane]);

    // stage-1 sparse row of this lane (lane == target node t)
    int s0 = 0, s1 = 0, s2 = 0;
    float aw0 = 0.f, aw1 = 0.f, aw2 = 0.f;
    if (lane < 21) {
        s0  = cIdx[lane*3];  s1  = cIdx[lane*3+1];  s2  = cIdx[lane*3+2];
        aw0 = cWt[lane*3];   aw1 = cWt[lane*3+1];   aw2 = cWt[lane*3+2];
    }

    __syncthreads();

    // this warp's 8 graphs
    const int g0 = (blockIdx.x * NWARP + warp) * 8;

    // ---- stage 1: y = A_norm @ x via shuffles; y stays in lane-t registers ----
    float yx[8], yy[8];
    #pragma unroll
    for (int h = 0; h < 2; h++) {
        float2 xv[4];
        #pragma unroll
        for (int j = 0; j < 4; j++) {
            const int g = g0 + 4*h + j;
            xv[j] = (lane < 21 && g < G)
                    ? ((const float2*)x)[(size_t)g * 21 + lane]
                    : make_float2(0.f, 0.f);
        }
        #pragma unroll
        for (int j = 0; j < 4; j++) {
            float xs0x = __shfl_sync(FULLMASK, xv[j].x, s0);
            float xs0y = __shfl_sync(FULLMASK, xv[j].y, s0);
            float xs1x = __shfl_sync(FULLMASK, xv[j].x, s1);
            float xs1y = __shfl_sync(FULLMASK, xv[j].y, s1);
            float xs2x = __shfl_sync(FULLMASK, xv[j].x, s2);
            float xs2y = __shfl_sync(FULLMASK, xv[j].y, s2);
            yx[4*h + j] = fmaf(aw2, xs2x, fmaf(aw1, xs1x, aw0 * xs0x));
            yy[4*h + j] = fmaf(aw2, xs2y, fmaf(aw1, xs1y, aw0 * xs0y));
        }
    }

    // ---- stage 2: p = c^T relu(y@W1 + b1); y broadcast from lane t via shfl ----
    ull pA[4] = {0,0,0,0}, pB[4] = {0,0,0,0};
    #pragma unroll 7
    for (int t = 0; t < 21; t++) {
        const float ch = cPoolH[t];
        const ull ct2 = pk2(ch, ch);
        #pragma unroll
        for (int jp = 0; jp < 4; jp++) {
            float xlo = __shfl_sync(FULLMASK, yx[2*jp],     t);
            float xhi = __shfl_sync(FULLMASK, yx[2*jp + 1], t);
            float ylo = __shfl_sync(FULLMASK, yy[2*jp],     t);
            float yhi = __shfl_sync(FULLMASK, yy[2*jp + 1], t);
            const ull x2 = pk2(xlo, xhi);
            const ull y2 = pk2(ylo, yhi);
            ull ha = fma2(x2, w1a0d, b1ad);
            ha = fma2(y2, w1a1d, ha);
            ha = add2(ha, ha & ABSMASK);          // 2*relu
            pA[jp] = fma2(ct2, ha, pA[jp]);       // ct2 pre-halved
            ull hb = fma2(x2, w1b0d, b1bd);
            hb = fma2(y2, w1b1d, hb);
            hb = add2(hb, hb & ABSMASK);
            pB[jp] = fma2(ct2, hb, pB[jp]);
        }
    }

    // ---- publish p to shared: psh[warp][k][j], k = lane / lane+32 ----
    #pragma unroll
    for (int jp = 0; jp < 4; jp++) {
        *(ull*)&psh[warp][lane][2*jp]      = pA[jp];
        *(ull*)&psh[warp][lane + 32][2*jp] = pB[jp];
    }
    __syncwarp();

    // ---- stage 3: out = p @ W2 + b2; acc packed over graph pairs ----
    ull acc[4][4];
    #pragma unroll
    for (int jp = 0; jp < 4; jp++)
        #pragma unroll
        for (int c = 0; c < 4; c++) acc[jp][c] = 0ull;

    #pragma unroll 8
    for (int k = 0; k < 64; k++) {
        const float4 w4 = W2s[k*32 + lane];             // lane's 4 output cols
        const ull wx = pk2(w4.x, w4.x);
        const ull wy = pk2(w4.y, w4.y);
        const ull wz = pk2(w4.z, w4.z);
        const ull ww = pk2(w4.w, w4.w);
        const ulonglong2 q03 = *(const ulonglong2*)&psh[warp][k][0];  // {p0p1, p2p3}
        const ulonglong2 q47 = *(const ulonglong2*)&psh[warp][k][4];  // {p4p5, p6p7}
        acc[0][0] = fma2(q03.x, wx, acc[0][0]);
        acc[0][1] = fma2(q03.x, wy, acc[0][1]);
        acc[0][2] = fma2(q03.x, wz, acc[0][2]);
        acc[0][3] = fma2(q03.x, ww, acc[0][3]);
        acc[1][0] = fma2(q03.y, wx, acc[1][0]);
        acc[1][1] = fma2(q03.y, wy, acc[1][1]);
        acc[1][2] = fma2(q03.y, wz, acc[1][2]);
        acc[1][3] = fma2(q03.y, ww, acc[1][3]);
        acc[2][0] = fma2(q47.x, wx, acc[2][0]);
        acc[2][1] = fma2(q47.x, wy, acc[2][1]);
        acc[2][2] = fma2(q47.x, wz, acc[2][2]);
        acc[2][3] = fma2(q47.x, ww, acc[2][3]);
        acc[3][0] = fma2(q47.y, wx, acc[3][0]);
        acc[3][1] = fma2(q47.y, wy, acc[3][1]);
        acc[3][2] = fma2(q47.y, wz, acc[3][2]);
        acc[3][3] = fma2(q47.y, ww, acc[3][3]);
    }

    // ---- epilogue: unpack pairs, add b2, store float4 per graph ----
    const float4 b2v = ((const float4*)b2)[lane];
    #pragma unroll
    for (int jp = 0; jp < 4; jp++) {
        float lo0, hi0, lo1, hi1, lo2, hi2, lo3, hi3;
        up2(acc[jp][0], lo0, hi0);
        up2(acc[jp][1], lo1, hi1);
        up2(acc[jp][2], lo2, hi2);
        up2(acc[jp][3], lo3, hi3);
        const int ga = g0 + 2*jp, gb = ga + 1;
        if (ga < G) {
            float4 o = make_float4(lo0 + b2v.x, lo1 + b2v.y, lo2 + b2v.z, lo3 + b2v.w);
            ((float4*)out)[(size_t)ga * 32 + lane] = o;
        }
        if (gb < G) {
            float4 o = make_float4(hi0 + b2v.x, hi1 + b2v.y, hi2 + b2v.z, hi3 + b2v.w);
            ((float4*)out)[(size_t)gb * 32 + lane] = o;
        }
    }
}

extern "C" void kernel_launch(void* const* d_in, const int* in_sizes, int n_in,
                              void* d_out, int out_size) {
    const float* x  = (const float*)d_in[0];
    const float* W1 = (const float*)d_in[1];
    const float* b1 = (const float*)d_in[2];
    const float* W2 = (const float*)d_in[3];
    const float* b2 = (const float*)d_in[4];
    float* out = (float*)d_out;

    const int G = in_sizes[0] / 42;            // graphs = B*S = 32768
    const int blocks = (G + 63) / 64;          // 8 graphs/warp * 8 warps = 64/CTA

    gnn_kernel<<<blocks, THREADS>>>(x, W1, b1, W2, b2, out, G);
}